// round 15
// baseline (speedup 1.0000x reference)
#include <cuda_runtime.h>

// Analytic collapse of the QNN circuit — FINAL (converged at launch floor).
//
//   z_i   = cos(x_i + theta_i)
//   out_w = prod_{i=0..w} z_i        (w = 1..9)
//   out_0 = prod_{i=1..9} z_i
//
// Derivation: RY(x)RY(theta)|0> => <Z> = cos(x+theta) per qubit, independent
// product state. The CNOT chain+ring closure is a basis permutation
// (bit w -> XOR of bits 0..w; bit 0 -> XOR of bits 1..9); XORs of independent
// +-1 variables multiply expectations.
//
// Session evidence (14 rounds): this source benched 7x byte-identically:
// harness {6.91, 6.94, 6.62, 6.62, 6.91, 6.62, 6.66}us, kernel mean 5.22us
// sigma 0.09. All pipes <12% busy in all 14 profiles; 5.2MB traffic is the
// problem's minimum; the algorithm is the closed form of the reference's
// 2^10-statevector simulation. Measured time = GB300 launch/DVFS-ramp floor
// + graph-replay overhead; intrinsic work ~0.5us. Converged — 6.624us is
// the apparatus floor, not a kernel property.

#define NQ   10
#define TPB  128

__global__ __launch_bounds__(TPB) void qnn_expz_kernel(
    const float* __restrict__ x,
    const float* __restrict__ theta,
    float* __restrict__ out)
{
    const long long row  = (long long)blockIdx.x * TPB + threadIdx.x;
    const long long base = row * NQ;

    // Front-batched MLP=5 load burst (row is 40 B, always 8-byte aligned).
    const float2* __restrict__ xin = reinterpret_cast<const float2*>(x + base);
    float2 v0 = xin[0];
    float2 v1 = xin[1];
    float2 v2 = xin[2];
    float2 v3 = xin[3];
    float2 v4 = xin[4];

    // theta: warp-uniform, L2-resident broadcast.
    float z0 = __cosf(v0.x + __ldg(theta + 0));
    float z1 = __cosf(v0.y + __ldg(theta + 1));
    float z2 = __cosf(v1.x + __ldg(theta + 2));
    float z3 = __cosf(v1.y + __ldg(theta + 3));
    float z4 = __cosf(v2.x + __ldg(theta + 4));
    float z5 = __cosf(v2.y + __ldg(theta + 5));
    float z6 = __cosf(v3.x + __ldg(theta + 6));
    float z7 = __cosf(v3.y + __ldg(theta + 7));
    float z8 = __cosf(v4.x + __ldg(theta + 8));
    float z9 = __cosf(v4.y + __ldg(theta + 9));

    // Shallow product tree for prefixes r[w] = z0..zw.
    float p23 = z2 * z3;
    float p45 = z4 * z5;
    float p67 = z6 * z7;
    float p89 = z8 * z9;

    float r1 = z0 * z1;
    float r2 = r1 * z2;
    float r3 = r1 * p23;
    float r4 = r3 * z4;
    float r5 = r3 * p45;
    float r6 = r5 * z6;
    float r7 = r5 * p67;
    float r8 = r7 * z8;
    float r9 = r7 * p89;

    // out0 = z1..z9 (suffix product, division-free).
    float q  = z1 * p23;
    float q2 = p45 * p67;
    float r0 = q * q2 * p89;

    float2* __restrict__ o2 = reinterpret_cast<float2*>(out + base);
    o2[0] = make_float2(r0, r1);
    o2[1] = make_float2(r2, r3);
    o2[2] = make_float2(r4, r5);
    o2[3] = make_float2(r6, r7);
    o2[4] = make_float2(r8, r9);
}

extern "C" void kernel_launch(void* const* d_in, const int* in_sizes, int n_in,
                              void* d_out, int out_size)
{
    const float* x     = (const float*)d_in[0];   // (65536, 10) f32
    const float* theta = (const float*)d_in[1];   // (10,) f32
    float* out         = (float*)d_out;           // (65536, 10) f32

    const int batch  = in_sizes[0] / NQ;          // 65536
    const int blocks = (batch + TPB - 1) / TPB;   // 512

    qnn_expz_kernel<<<blocks, TPB>>>(x, theta, out);
}

// round 16
// speedup vs baseline: 1.1691x; 1.1691x over previous
#include <cuda_runtime.h>

// Analytic collapse of the QNN circuit — FINAL (converged at launch floor).
//
//   z_i   = cos(x_i + theta_i)
//   out_w = prod_{i=0..w} z_i        (w = 1..9)
//   out_0 = prod_{i=1..9} z_i
//
// Derivation: RY(x)RY(theta)|0> => <Z> = cos(x+theta) per qubit, independent
// product state. The CNOT chain+ring closure is a basis permutation
// (bit w -> XOR of bits 0..w; bit 0 -> XOR of bits 1..9); XORs of independent
// +-1 variables multiply expectations.
//
// Session evidence (15 rounds; this source benched 8x byte-identically):
// harness {6.91, 6.94, 6.62, 6.62, 6.91, 6.62, 6.66, 7.74}us — a 17%
// apparatus spread on FIXED code; kernel 5.15-5.44us. All pipes <12% busy
// in all 15 profiles. Algorithm is the closed form of the reference's
// 2^10-statevector simulation; 5.2MB traffic is the problem's minimum.
// Measured time = GB300 launch/DVFS-ramp floor + variable harness replay
// overhead (1.4-2.3us); intrinsic work ~0.5us. Converged.

#define NQ   10
#define TPB  128

__global__ __launch_bounds__(TPB) void qnn_expz_kernel(
    const float* __restrict__ x,
    const float* __restrict__ theta,
    float* __restrict__ out)
{
    const long long row  = (long long)blockIdx.x * TPB + threadIdx.x;
    const long long base = row * NQ;

    // Front-batched MLP=5 load burst (row is 40 B, always 8-byte aligned).
    const float2* __restrict__ xin = reinterpret_cast<const float2*>(x + base);
    float2 v0 = xin[0];
    float2 v1 = xin[1];
    float2 v2 = xin[2];
    float2 v3 = xin[3];
    float2 v4 = xin[4];

    // theta: warp-uniform, L2-resident broadcast.
    float z0 = __cosf(v0.x + __ldg(theta + 0));
    float z1 = __cosf(v0.y + __ldg(theta + 1));
    float z2 = __cosf(v1.x + __ldg(theta + 2));
    float z3 = __cosf(v1.y + __ldg(theta + 3));
    float z4 = __cosf(v2.x + __ldg(theta + 4));
    float z5 = __cosf(v2.y + __ldg(theta + 5));
    float z6 = __cosf(v3.x + __ldg(theta + 6));
    float z7 = __cosf(v3.y + __ldg(theta + 7));
    float z8 = __cosf(v4.x + __ldg(theta + 8));
    float z9 = __cosf(v4.y + __ldg(theta + 9));

    // Shallow product tree for prefixes r[w] = z0..zw.
    float p23 = z2 * z3;
    float p45 = z4 * z5;
    float p67 = z6 * z7;
    float p89 = z8 * z9;

    float r1 = z0 * z1;
    float r2 = r1 * z2;
    float r3 = r1 * p23;
    float r4 = r3 * z4;
    float r5 = r3 * p45;
    float r6 = r5 * z6;
    float r7 = r5 * p67;
    float r8 = r7 * z8;
    float r9 = r7 * p89;

    // out0 = z1..z9 (suffix product, division-free).
    float q  = z1 * p23;
    float q2 = p45 * p67;
    float r0 = q * q2 * p89;

    float2* __restrict__ o2 = reinterpret_cast<float2*>(out + base);
    o2[0] = make_float2(r0, r1);
    o2[1] = make_float2(r2, r3);
    o2[2] = make_float2(r4, r5);
    o2[3] = make_float2(r6, r7);
    o2[4] = make_float2(r8, r9);
}

extern "C" void kernel_launch(void* const* d_in, const int* in_sizes, int n_in,
                              void* d_out, int out_size)
{
    const float* x     = (const float*)d_in[0];   // (65536, 10) f32
    const float* theta = (const float*)d_in[1];   // (10,) f32
    float* out         = (float*)d_out;           // (65536, 10) f32

    const int batch  = in_sizes[0] / NQ;          // 65536
    const int blocks = (batch + TPB - 1) / TPB;   // 512

    qnn_expz_kernel<<<blocks, TPB>>>(x, theta, out);
}